// round 8
// baseline (speedup 1.0000x reference)
#include <cuda_runtime.h>
#include <math.h>

#define NN 512
#define SS 64
#define CC 1024
#define BB 10
#define SB 4                        // s-positions per CTA
#define CHUNKS (SS / SB)            // 16 CTAs per row
#define PI_ELEMS (NN * SS * CC)

__device__ unsigned char g_counts[NN * CC];   // row histograms, u8 (<=63)
__device__ float         g_lse[NN * SS];      // per-(n,s) log-partition
__device__ int           g_flag[NN];          // zero-init; re-set to same value
                                              // every replay (benign same-value race)

__device__ __forceinline__ int ld_acquire_gpu(const int* p) {
    int v;
    asm volatile("ld.global.acquire.gpu.b32 %0, [%1];" : "=r"(v) : "l"(p));
    return v;
}

// ---------------------------------------------------------------------------
// Single kernel, 8192 CTAs x 256 threads.
//  chunk 0 of each row  = producer: hist -> Z -> 64 lse -> publish + flag,
//                         then stream its own 4 s-positions from smem.
//  chunks 1..15         = consumer: build ban mask, acquire-spin on flag,
//                         then the proven streaming loop (R4 pattern).
// Consumer bid > producer bid within a row and CTAs dispatch in bid order,
// so every resident consumer's producer is resident -> no deadlock.
// ---------------------------------------------------------------------------
__global__ __launch_bounds__(256) void spop_kernel(
    const int* __restrict__ ban_ids,
    const int* __restrict__ item_ids,
    float* __restrict__ out)
{
    __shared__ unsigned s_mask[SB][CC / 32];

    const int blk   = blockIdx.x;
    const int n     = blk >> 4;               // CHUNKS == 16
    const int chunk = blk & 15;
    const int s0    = chunk * SB;
    const int tid   = threadIdx.x;
    const int c0    = tid * 4;

    if (chunk == 0) {
        // ================= PRODUCER =================
        __shared__ int   s_hist[CC];
        __shared__ int   s_ids[SS];
        __shared__ int   s_ban[SS * BB];
        __shared__ float s_lse[SS];
        __shared__ int   s_last;
        __shared__ float s_red[8];
        __shared__ float s_Z;

        const int lane = tid & 31;
        const int wrp  = tid >> 5;

        #pragma unroll
        for (int i = tid; i < CC; i += 256) s_hist[i] = 0;
        if (tid < SS) s_ids[tid] = item_ids[n * SS + tid];
        #pragma unroll
        for (int i = tid; i < SS * BB; i += 256) s_ban[i] = ban_ids[n * SS * BB + i];
        if (tid < SB * (CC / 32)) (&s_mask[0][0])[tid] = 0u;
        if (tid == 0) s_last = -1;
        if (tid < SS) out[PI_ELEMS + n * SS + tid] = 0.0f;   // v tail zeros
        __syncthreads();

        if (tid < SS && s_ids[tid] != 0) atomicMax(&s_last, tid);  // PAD == 0
        if (tid < SB * BB) {                                       // own-chunk mask
            const int b = s_ban[tid];
            atomicOr(&s_mask[tid / BB][b >> 5], 1u << (b & 31));
        }
        __syncthreads();

        if (tid < SS && s_ids[tid] != 0 && tid != s_last)
            atomicAdd(&s_hist[s_ids[tid]], 1);
        __syncthreads();

        const int h0 = s_hist[c0 + 0], h1 = s_hist[c0 + 1];
        const int h2 = s_hist[c0 + 2], h3 = s_hist[c0 + 3];
        reinterpret_cast<unsigned*>(g_counts)[n * (CC / 4) + tid] =
            (unsigned)h0 | ((unsigned)h1 << 8) | ((unsigned)h2 << 16) | ((unsigned)h3 << 24);

        float z = expf((float)h0) + expf((float)h1) + expf((float)h2) + expf((float)h3);
        #pragma unroll
        for (int off = 16; off; off >>= 1)
            z += __shfl_xor_sync(0xffffffffu, z, off);
        if (lane == 0) s_red[wrp] = z;
        __syncthreads();
        if (tid == 0) {
            float t = 0.0f;
            #pragma unroll
            for (int w = 0; w < 8; ++w) t += s_red[w];
            s_Z = t;
        }
        __syncthreads();

        if (tid < SS) {
            const float Z = s_Z;
            float corr = 0.0f;
            int ids[BB];
            #pragma unroll
            for (int j = 0; j < BB; ++j) {
                const int id = s_ban[tid * BB + j];
                ids[j] = id;
                bool dup = false;
                #pragma unroll
                for (int k = 0; k < BB; ++k) if (k < j) dup |= (ids[k] == id);
                if (!dup) corr += expf((float)s_hist[id]);
            }
            const float l = logf(fmaxf(Z - corr, 1e-35f));
            s_lse[tid] = l;
            g_lse[n * SS + tid] = l;
        }
        __syncthreads();

        if (tid == 0) {                       // release the row
            __threadfence();
            atomicExch(&g_flag[n], 1);
        }

        // stream own chunk (s0 == 0) straight from smem
        const float f0 = (float)h0, f1 = (float)h1;
        const float f2 = (float)h2, f3 = (float)h3;
        float4* __restrict__ out4 =
            reinterpret_cast<float4*>(out) + (n * SS) * (CC / 4) + tid;
        #pragma unroll
        for (int s = 0; s < SB; ++s) {
            const float    l = s_lse[s];
            const unsigned m = s_mask[s][c0 >> 5] >> (c0 & 31);
            float4 o;
            o.x = f0 - l - ((m & 1u) ? 1e9f : 0.0f);
            o.y = f1 - l - ((m & 2u) ? 1e9f : 0.0f);
            o.z = f2 - l - ((m & 4u) ? 1e9f : 0.0f);
            o.w = f3 - l - ((m & 8u) ? 1e9f : 0.0f);
            out4[s * (CC / 4)] = o;
        }
    } else {
        // ================= CONSUMER =================
        __shared__ float s_l[SB];

        if (tid < SB * (CC / 32)) (&s_mask[0][0])[tid] = 0u;
        int myban = 0;
        if (tid < SB * BB) myban = ban_ids[(n * SS + s0) * BB + tid];
        __syncthreads();
        if (tid < SB * BB)
            atomicOr(&s_mask[tid / BB][myban >> 5], 1u << (myban & 31));

        if (tid == 0) {                       // acquire-spin on the row flag
            while (ld_acquire_gpu(&g_flag[n]) == 0) __nanosleep(64);
        }
        __syncthreads();                      // orders mask + publishes acquire

        const unsigned cw =
            __ldg(&reinterpret_cast<const unsigned*>(g_counts)[n * (CC / 4) + tid]);
        if (tid < SB) s_l[tid] = g_lse[n * SS + s0 + tid];
        __syncthreads();

        const float f0 = (float)( cw        & 0xffu);
        const float f1 = (float)((cw >>  8) & 0xffu);
        const float f2 = (float)((cw >> 16) & 0xffu);
        const float f3 = (float)( cw >> 24         );

        float4* __restrict__ out4 =
            reinterpret_cast<float4*>(out) + (n * SS + s0) * (CC / 4) + tid;
        #pragma unroll
        for (int s = 0; s < SB; ++s) {
            const float    l = s_l[s];
            const unsigned m = s_mask[s][c0 >> 5] >> (c0 & 31);
            float4 o;
            o.x = f0 - l - ((m & 1u) ? 1e9f : 0.0f);
            o.y = f1 - l - ((m & 2u) ? 1e9f : 0.0f);
            o.z = f2 - l - ((m & 4u) ? 1e9f : 0.0f);
            o.w = f3 - l - ((m & 8u) ? 1e9f : 0.0f);
            out4[s * (CC / 4)] = o;
        }
    }
}

extern "C" void kernel_launch(void* const* d_in, const int* in_sizes, int n_in,
                              void* d_out, int out_size) {
    // metadata order: null_w (f32, unused), ban_ids (i32 [N,S,B]), item_ids (i32 [N,S])
    const int* ban_ids  = (const int*)d_in[1];
    const int* item_ids = (const int*)d_in[2];
    float* out = (float*)d_out;

    spop_kernel<<<NN * CHUNKS, 256>>>(ban_ids, item_ids, out);
}

// round 9
// speedup vs baseline: 1.0849x; 1.0849x over previous
#include <cuda_runtime.h>
#include <math.h>

#define NN 512
#define SS 64
#define CC 1024
#define BB 10
#define SB 4                        // s-positions per streaming CTA
#define PI_ELEMS (NN * SS * CC)
#define TILE_BYTES (SB * CC * 4)    // 16 KB per CTA

__device__ unsigned char g_counts[NN * CC];   // row histograms, u8 (<=63)
__device__ float         g_lse[NN * SS];      // per-(n,s) log-partition

__device__ __forceinline__ unsigned smem_u32(const void* p) {
    unsigned a;
    asm("{ .reg .u64 t; cvta.to.shared.u64 t, %1; cvt.u32.u64 %0, t; }"
        : "=r"(a) : "l"(p));
    return a;
}

// ---------------------------------------------------------------------------
// Kernel A (primary): per-row hist + Z + all 64 lse + v zeros. 512 CTAs.
// ---------------------------------------------------------------------------
__global__ __launch_bounds__(256) void row_stats_kernel(
    const int* __restrict__ ban_ids,
    const int* __restrict__ item_ids,
    float* __restrict__ out)
{
    __shared__ int   s_hist[CC];
    __shared__ int   s_ids[SS];
    __shared__ int   s_ban[SS * BB];
    __shared__ int   s_last;
    __shared__ float s_red[8];
    __shared__ float s_Z;

    const int n    = blockIdx.x;
    const int tid  = threadIdx.x;
    const int lane = tid & 31;
    const int wrp  = tid >> 5;

    #pragma unroll
    for (int i = tid; i < CC; i += 256) s_hist[i] = 0;
    if (tid < SS) s_ids[tid] = item_ids[n * SS + tid];
    #pragma unroll
    for (int i = tid; i < SS * BB; i += 256) s_ban[i] = ban_ids[n * SS * BB + i];
    if (tid == 0) s_last = -1;
    if (tid < SS) out[PI_ELEMS + n * SS + tid] = 0.0f;     // v tail zeros
    __syncthreads();

    if (tid < SS && s_ids[tid] != 0) atomicMax(&s_last, tid);   // PAD == 0
    __syncthreads();

    if (tid < SS && s_ids[tid] != 0 && tid != s_last)
        atomicAdd(&s_hist[s_ids[tid]], 1);
    __syncthreads();

    const int c0 = tid * 4;
    const int h0 = s_hist[c0 + 0], h1 = s_hist[c0 + 1];
    const int h2 = s_hist[c0 + 2], h3 = s_hist[c0 + 3];
    reinterpret_cast<unsigned*>(g_counts)[n * (CC / 4) + tid] =
        (unsigned)h0 | ((unsigned)h1 << 8) | ((unsigned)h2 << 16) | ((unsigned)h3 << 24);

    float z = expf((float)h0) + expf((float)h1) + expf((float)h2) + expf((float)h3);
    #pragma unroll
    for (int off = 16; off; off >>= 1)
        z += __shfl_xor_sync(0xffffffffu, z, off);
    if (lane == 0) s_red[wrp] = z;
    __syncthreads();
    if (tid == 0) {
        float t = 0.0f;
        #pragma unroll
        for (int w = 0; w < 8; ++w) t += s_red[w];
        s_Z = t;
    }
    __syncthreads();

    if (tid < SS) {
        const float Z = s_Z;
        float corr = 0.0f;
        int ids[BB];
        #pragma unroll
        for (int j = 0; j < BB; ++j) {
            const int id = s_ban[tid * BB + j];
            ids[j] = id;
            bool dup = false;
            #pragma unroll
            for (int k = 0; k < BB; ++k) if (k < j) dup |= (ids[k] == id);
            if (!dup) corr += expf((float)s_hist[id]);
        }
        g_lse[n * SS + tid] = logf(fmaxf(Z - corr, 1e-35f));
    }
}

// ---------------------------------------------------------------------------
// Kernel B (secondary, PDL): TMA-bulk-store streamer. 8192 CTAs x 256 thr.
// Compute the 16KB tile in smem (STS.128), then ONE cp.async.bulk per CTA
// SMEM -> GMEM: bypasses L1tex and the 12-cyc/STG.128 LSU issue cost.
// ---------------------------------------------------------------------------
__global__ __launch_bounds__(256) void stream_kernel(
    const int* __restrict__ ban_ids,
    float* __restrict__ out)
{
    __shared__ alignas(128) float s_tile[SB * CC];       // 16 KB
    __shared__ unsigned s_mask[SB][CC / 32];
    __shared__ float    s_l[SB];

    const int blk = blockIdx.x;
    const int n   = blk >> 4;                 // SS/SB == 16 chunks per row
    const int s0  = (blk & 15) * SB;
    const int tid = threadIdx.x;
    const int c0  = tid * 4;

    // ---- A-independent prologue (overlaps row_stats under PDL) ----
    if (tid < SB * (CC / 32))
        (&s_mask[0][0])[tid] = 0u;
    int myban = 0;
    if (tid < SB * BB) myban = ban_ids[(n * SS + s0) * BB + tid];
    __syncthreads();
    if (tid < SB * BB)
        atomicOr(&s_mask[tid / BB][myban >> 5], 1u << (myban & 31));

    // ---- wait for kernel A's g_counts / g_lse ----
    cudaGridDependencySynchronize();

    const unsigned cw =
        __ldg(&reinterpret_cast<const unsigned*>(g_counts)[n * (CC / 4) + tid]);
    if (tid < SB) s_l[tid] = g_lse[n * SS + s0 + tid];
    __syncthreads();

    const float f0 = (float)( cw        & 0xffu);
    const float f1 = (float)((cw >>  8) & 0xffu);
    const float f2 = (float)((cw >> 16) & 0xffu);
    const float f3 = (float)( cw >> 24         );

    float4* __restrict__ tile4 = reinterpret_cast<float4*>(s_tile);
    #pragma unroll
    for (int s = 0; s < SB; ++s) {
        const float    l = s_l[s];
        const unsigned m = s_mask[s][c0 >> 5] >> (c0 & 31);
        float4 o;
        o.x = f0 - l - ((m & 1u) ? 1e9f : 0.0f);
        o.y = f1 - l - ((m & 2u) ? 1e9f : 0.0f);
        o.z = f2 - l - ((m & 4u) ? 1e9f : 0.0f);
        o.w = f3 - l - ((m & 8u) ? 1e9f : 0.0f);
        tile4[s * (CC / 4) + tid] = o;        // STS.128, conflict-free
    }
    __syncthreads();                          // tile complete

    if (tid == 0) {
        float* dst = out + (n * SS + s0) * CC;
        const unsigned src = smem_u32(s_tile);
        asm volatile("fence.proxy.async.shared::cta;" ::: "memory");
        asm volatile(
            "cp.async.bulk.global.shared::cta.bulk_group [%0], [%1], %2;"
            :: "l"(dst), "r"(src), "r"((int)TILE_BYTES) : "memory");
        asm volatile("cp.async.bulk.commit_group;" ::: "memory");
        asm volatile("cp.async.bulk.wait_group 0;" ::: "memory");
    }
}

extern "C" void kernel_launch(void* const* d_in, const int* in_sizes, int n_in,
                              void* d_out, int out_size) {
    // metadata order: null_w (f32, unused), ban_ids (i32 [N,S,B]), item_ids (i32 [N,S])
    const int* ban_ids  = (const int*)d_in[1];
    const int* item_ids = (const int*)d_in[2];
    float* out = (float*)d_out;

    row_stats_kernel<<<NN, 256>>>(ban_ids, item_ids, out);

    cudaLaunchAttribute attr[1];
    attr[0].id = cudaLaunchAttributeProgrammaticStreamSerialization;
    attr[0].val.programmaticStreamSerializationAllowed = 1;

    cudaLaunchConfig_t cfg = {};
    cfg.gridDim  = dim3(NN * (SS / SB), 1, 1);
    cfg.blockDim = dim3(256, 1, 1);
    cfg.dynamicSmemBytes = 0;
    cfg.stream   = 0;
    cfg.attrs    = attr;
    cfg.numAttrs = 1;

    cudaLaunchKernelEx(&cfg, stream_kernel, ban_ids, (float*)out);
}